// round 16
// baseline (speedup 1.0000x reference)
#include <cuda_runtime.h>
#include <cstdint>

// QRegulariser: out = mean_b( 1 - prod_q cos^2( (hidden@W.T + b)_q / 2 ) )
// B=65536, H=1024, Q=8. DRAM-streaming kernel at the chip's practical ceiling.
//
// R16 = R15 (dynamic tickets; ncu 46.2us, DRAM 74.6%) + CHUNK_T 2->4:
//  - each ticket = 4 tiles = 256KB contiguous per SM; chip-wide ticket order
//    stays roughly address-sequential (DRAM row-buffer friendly).
//  - 1 ATOMG per 4 tiles, prefetched before issue -> producer purely
//    mbarrier-paced between tickets.
//  - unchanged: NBUF=3 x 64KB tiles, 16x4KB cp.async.bulk, padded rows
//    (conflict-free LDS), 8 consumer warps (K-split 128), rotated
//    off-critical-path epilogue, m16n8k8 tf32 HMMA.

#define HDIM 1024
#define QDIM 8
#define TILE_ROWS 16
#define ROW_BYTES (HDIM * 4)             // 4096
#define ROW_PAD 16
#define ROW_STRIDE (ROW_BYTES + ROW_PAD) // 4112
#define TILE_SMEM (TILE_ROWS * ROW_STRIDE)   // 65792
#define NBUF 3
#define NCONS 8
#define NTHREADS ((NCONS + 1) * 32)      // 288
#define GRID_SMS 148
#define SLICES_PER_WARP 16               // 128 k-slices / 8 warps
#define CHUNK_T 4                        // tiles per ticket
#define DSMEM_BYTES (NBUF * TILE_SMEM + 1024)  // 198400

__device__ double g_partials[GRID_SMS];
__device__ unsigned int g_counter = 0;
__device__ unsigned int g_ticket = 0;

__device__ __forceinline__ uint32_t smem_u32(const void* p) {
    uint32_t a;
    asm("{ .reg .u64 t; cvta.to.shared.u64 t, %1; cvt.u32.u64 %0, t; }" : "=r"(a) : "l"(p));
    return a;
}
__device__ __forceinline__ uint32_t elect_one() {
    uint32_t p;
    asm volatile("{ .reg .pred p; elect.sync _|p, 0xFFFFFFFF; selp.b32 %0, 1, 0, p; }" : "=r"(p));
    return p;
}
#define MBARRIER_INIT(a, n) \
    asm volatile("mbarrier.init.shared.b64 [%0], %1;" :: "r"(a), "r"((uint32_t)(n)) : "memory")
#define MBARRIER_EXPECT_TX(a, tx) \
    asm volatile("mbarrier.arrive.expect_tx.shared.b64 _, [%0], %1;" :: "r"(a), "r"((uint32_t)(tx)) : "memory")
#define MBARRIER_ARRIVE(a) \
    asm volatile("mbarrier.arrive.shared.b64 _, [%0];" :: "r"(a) : "memory")
#define MBAR_WAIT(a, par) do {                                              \
    uint32_t _m = (a), _p = (par), _d;                                      \
    asm volatile("{ .reg .pred p; mbarrier.try_wait.parity.acquire.cta.shared::cta.b64 p, [%1], %2;" \
                 " selp.b32 %0, 1, 0, p; }" : "=r"(_d) : "r"(_m), "r"(_p) : "memory");             \
    if (!_d) {                                                              \
        asm volatile("{ .reg .pred P1; WL_%=: mbarrier.try_wait.parity.acquire.cta.shared::cta.b64 P1, [%0], %1, 0x989680;" \
                     " @P1 bra.uni WD_%=; bra.uni WL_%=; WD_%=: }" :: "r"(_m), "r"(_p) : "memory"); \
    } } while (0)
__device__ __forceinline__ void bulk_copy(uint32_t dst, const void* src,
                                          uint32_t bytes, uint32_t mbar) {
    asm volatile("cp.async.bulk.shared::cta.global.mbarrier::complete_tx::bytes "
                 "[%0], [%1], %2, [%3];"
                 :: "r"(dst), "l"(src), "r"(bytes), "r"(mbar) : "memory");
}
// D(16x8) += A(16x8) * B(8x8); tf32 inputs as raw f32 bit patterns.
__device__ __forceinline__ void mma_tf32(float4& d,
                                         uint32_t a0, uint32_t a1, uint32_t a2, uint32_t a3,
                                         uint32_t b0, uint32_t b1) {
    asm volatile(
        "mma.sync.aligned.m16n8k8.row.col.f32.tf32.tf32.f32 "
        "{%0,%1,%2,%3}, {%4,%5,%6,%7}, {%8,%9}, {%0,%1,%2,%3};"
        : "+f"(d.x), "+f"(d.y), "+f"(d.z), "+f"(d.w)
        : "r"(a0), "r"(a1), "r"(a2), "r"(a3), "r"(b0), "r"(b1));
}

__global__ __launch_bounds__(NTHREADS, 1)
void qreg_r16_kernel(const float* __restrict__ hidden,
                     const float* __restrict__ Wm,
                     const float* __restrict__ bv,
                     float* __restrict__ out,
                     int B) {
    extern __shared__ char dsm_raw[];
    __shared__ __align__(8) uint64_t mb_full[NBUF], mb_empty[NBUF];
    __shared__ int s_tileidx[NBUF];
    __shared__ float4 sPart[3][NCONS][32];        // 3 rotating slots
    __shared__ double warp_locals[NCONS];
    __shared__ unsigned int is_last;

    const int tid = threadIdx.x;
    const int warp = tid >> 5, lane = tid & 31;
    const int bid = blockIdx.x;

    // 1024-align dynamic smem.
    const uint32_t raw = smem_u32(dsm_raw);
    const uint32_t base = (raw + 1023u) & ~1023u;
    const uint32_t tiles_u = base;                 // 3 tile buffers
    char* tiles_g = dsm_raw + (base - raw);

    if (tid == 0) {
        #pragma unroll
        for (int b = 0; b < NBUF; ++b) {
            MBARRIER_INIT(smem_u32(&mb_full[b]), 1);       // tx completes it
            MBARRIER_INIT(smem_u32(&mb_empty[b]), NCONS);  // 1 arrive/consumer
        }
    }
    if (tid < NCONS) warp_locals[tid] = 0.0;
    __syncthreads();

    const int ntiles = (B + TILE_ROWS - 1) / TILE_ROWS;

    if (warp == NCONS) {
        // ---- Producer: dynamic chunks of CHUNK_T tiles via global ticket,
        // next ticket prefetched before issuing the current chunk.
        if (elect_one()) {
            int i = 0;   // issued-slot sequence (consumers track the same i)
            int c = (int)atomicAdd(&g_ticket, 1u);
            while (c * CHUNK_T < ntiles) {
                const int next = (int)atomicAdd(&g_ticket, 1u);  // prefetch
                const int tb = c * CHUNK_T;
                int te = tb + CHUNK_T; if (te > ntiles) te = ntiles;
                for (int t = tb; t < te; ++t, ++i) {
                    const int buf = i % NBUF;
                    const uint32_t epar = (((i / NBUF) & 1) ^ 1);  // 1st pass free
                    MBAR_WAIT(smem_u32(&mb_empty[buf]), epar);
                    s_tileidx[buf] = t;   // ordered by TMA-complete release
                    const int row0 = t * TILE_ROWS;
                    int nv = B - row0; if (nv > TILE_ROWS) nv = TILE_ROWS;
                    MBARRIER_EXPECT_TX(smem_u32(&mb_full[buf]),
                                       (uint32_t)nv * ROW_BYTES);
                    const uint32_t dst0 = tiles_u + (uint32_t)buf * TILE_SMEM;
                    const char* src0 = (const char*)hidden
                                     + (size_t)row0 * ROW_BYTES;
                    #pragma unroll
                    for (int r = 0; r < TILE_ROWS; ++r) {
                        if (r < nv)
                            bulk_copy(dst0 + (uint32_t)r * ROW_STRIDE,
                                      src0 + (size_t)r * ROW_BYTES,
                                      ROW_BYTES, smem_u32(&mb_full[buf]));
                    }
                }
                c = next;
            }
            // Sentinel: complete the next slot without TMA.
            const int buf = i % NBUF;
            const uint32_t epar = (((i / NBUF) & 1) ^ 1);
            MBAR_WAIT(smem_u32(&mb_empty[buf]), epar);
            s_tileidx[buf] = -1;
            MBARRIER_ARRIVE(smem_u32(&mb_full[buf]));   // release + complete
        }
    } else {
        // ---- Consumer warp w: K-range [w*128, (w+1)*128) of every tile.
        const int rl = lane >> 2;           // fragment row 0..7
        const int kl = lane & 3;            // fragment k-lane 0..3
        const float b0v = bv[2 * kl];
        const float b1v = bv[2 * kl + 1];

        // B fragments in registers: slice j (global slice s = warp*16 + j):
        // b0 = W[lane/4][8s + lane%4], b1 = W[lane/4][8s + lane%4 + 4].
        uint32_t bf0[SLICES_PER_WARP], bf1[SLICES_PER_WARP];
        {
            const int n = lane >> 2;
            const float* wr = Wm + n * HDIM + (warp * SLICES_PER_WARP) * 8 + kl;
            #pragma unroll
            for (int j = 0; j < SLICES_PER_WARP; ++j) {
                bf0[j] = __float_as_uint(wr[j * 8]);
                bf1[j] = __float_as_uint(wr[j * 8 + 4]);
            }
        }

        double local = 0.0;
        for (int i = 0;; ++i) {
            const int buf = i % NBUF;
            const uint32_t fpar = (i / NBUF) & 1;
            MBAR_WAIT(smem_u32(&mb_full[buf]), fpar);
            const int t = s_tileidx[buf];
            if (t < 0) break;

            const char* Tb = tiles_g + buf * TILE_SMEM;
            const char* pa = Tb + rl * ROW_STRIDE + kl * 4
                           + warp * (SLICES_PER_WARP * 32);

            float4 acc0 = make_float4(0.f, 0.f, 0.f, 0.f);
            float4 acc1 = make_float4(0.f, 0.f, 0.f, 0.f);

            #pragma unroll
            for (int j = 0; j < SLICES_PER_WARP; ++j) {
                const char* p = pa + j * 32;
                const uint32_t a0 = *reinterpret_cast<const uint32_t*>(p);
                const uint32_t a1 = *reinterpret_cast<const uint32_t*>(p + 8 * ROW_STRIDE);
                const uint32_t a2 = *reinterpret_cast<const uint32_t*>(p + 16);
                const uint32_t a3 = *reinterpret_cast<const uint32_t*>(p + 8 * ROW_STRIDE + 16);
                float4& acc = (j & 1) ? acc1 : acc0;
                mma_tf32(acc, a0, a1, a2, a3, bf0[j], bf1[j]);
            }
            // Reads done -> free the buffer slot for the producer.
            if (elect_one()) MBARRIER_ARRIVE(smem_u32(&mb_empty[buf]));

            const int ps = i % 3;           // sPart rotating slot
            float4 acc;
            acc.x = acc0.x + acc1.x; acc.y = acc0.y + acc1.y;
            acc.z = acc0.z + acc1.z; acc.w = acc0.w + acc1.w;
            sPart[ps][warp][lane] = acc;
            // One consumer-scope barrier: all partials for tile i stored.
            asm volatile("bar.sync 1, %0;" :: "n"(NCONS * 32) : "memory");

            // Rotated epilogue: warp (i%8) handles tile i off-critical-path.
            if (warp == (i & 7)) {
                float4 a = sPart[ps][0][lane];
                #pragma unroll
                for (int w = 1; w < NCONS; ++w) {
                    const float4 b = sPart[ps][w][lane];
                    a.x += b.x; a.y += b.y; a.z += b.z; a.w += b.w;
                }
                const float tA0 = a.x + b0v, tA1 = a.y + b1v;
                const float tB0 = a.z + b0v, tB1 = a.w + b1v;
                float pA = 0.25f * (1.0f + __cosf(tA0)) * (1.0f + __cosf(tA1));
                float pB = 0.25f * (1.0f + __cosf(tB0)) * (1.0f + __cosf(tB1));
                #pragma unroll
                for (int d = 1; d <= 2; d <<= 1) {
                    pA *= __shfl_xor_sync(0xffffffffu, pA, d);
                    pB *= __shfl_xor_sync(0xffffffffu, pB, d);
                }
                const int rowA = t * TILE_ROWS + rl;
                const int rowB = rowA + 8;
                float sv = ((rowA < B) ? (1.0f - pA) : 0.0f)
                         + ((rowB < B) ? (1.0f - pB) : 0.0f);
                #pragma unroll
                for (int d = 1; d <= 16; d <<= 1)
                    sv += __shfl_xor_sync(0xffffffffu, sv, d);
                local += (double)sv * 0.25;   // quad replication
            }
        }
        if (lane == 0) warp_locals[warp] = local;
    }
    __syncthreads();

    if (tid == 0) {
        double bsum = 0.0;
        #pragma unroll
        for (int w = 0; w < NCONS; ++w) bsum += warp_locals[w];
        g_partials[bid] = bsum;
        __threadfence();
        const unsigned int prev = atomicAdd(&g_counter, 1u);
        is_last = (prev == gridDim.x - 1) ? 1u : 0u;
    }
    __syncthreads();

    if (is_last) {
        __threadfence();
        const volatile double* vp = g_partials;
        double ssum = 0.0;
        for (int i = tid; i < (int)gridDim.x; i += NTHREADS) ssum += vp[i];
        #pragma unroll
        for (int d = 16; d > 0; d >>= 1)
            ssum += __shfl_down_sync(0xffffffffu, ssum, d);
        __shared__ double fin[NCONS + 1];
        if (lane == 0) fin[warp] = ssum;
        __syncthreads();
        if (tid == 0) {
            double tt = 0.0;
            #pragma unroll
            for (int w = 0; w < NCONS + 1; ++w) tt += fin[w];
            out[0] = (float)(tt / (double)B);
            g_counter = 0;   // reset for graph replay
            g_ticket = 0;
        }
    }
}

extern "C" void kernel_launch(void* const* d_in, const int* in_sizes, int n_in,
                              void* d_out, int out_size) {
    const float* hidden = (const float*)d_in[0];   // [B, H] f32
    const float* Wm     = (const float*)d_in[1];   // [Q, H] f32
    const float* bv     = (const float*)d_in[2];   // [Q]    f32
    float* out = (float*)d_out;

    const int B = in_sizes[0] / HDIM;

    static bool attr_set = false;
    if (!attr_set) {
        cudaFuncSetAttribute(qreg_r16_kernel,
                             cudaFuncAttributeMaxDynamicSharedMemorySize,
                             DSMEM_BYTES);
        attr_set = true;
    }

    qreg_r16_kernel<<<GRID_SMS, NTHREADS, DSMEM_BYTES>>>(hidden, Wm, bv, out, B);
}

// round 17
// speedup vs baseline: 1.0087x; 1.0087x over previous
#include <cuda_runtime.h>
#include <cstdint>

// QRegulariser: out = mean_b( 1 - prod_q cos^2( (hidden@W.T + b)_q / 2 ) )
// B=65536, H=1024, Q=8. DRAM-streaming kernel at the chip's practical ceiling.
//
// R17 = R15 exactly (best measured: ncu 46.18us, DRAM 74.6%, 5.9TB/s).
// R16's CHUNK_T=4 regressed (71.9%) -> 2-tile tickets restored: finer tickets
// give more concurrent 128KB streams chip-wide (better HBM channel/bank
// interleave) and halve tail-imbalance granularity.
// Final design:
//  - producer warp streams 64KB tiles (16 x 4KB contiguous cp.async.bulk)
//    into a 3-deep smem ring; mbarrier expect_tx handshake.
//  - dynamic 2-tile tickets via prefetched global atomic (absorbs between-SM
//    speed variance + wave quantization; +4% DRAM vs static split).
//  - 8 consumer warps, K-split 128 els each, m16n8k8 tf32 HMMA (W fragments
//    register-resident), padded smem rows -> conflict-free LDS.
//  - rotated off-critical-path cos-product epilogue; last-block reduction.

#define HDIM 1024
#define QDIM 8
#define TILE_ROWS 16
#define ROW_BYTES (HDIM * 4)             // 4096
#define ROW_PAD 16
#define ROW_STRIDE (ROW_BYTES + ROW_PAD) // 4112
#define TILE_SMEM (TILE_ROWS * ROW_STRIDE)   // 65792
#define NBUF 3
#define NCONS 8
#define NTHREADS ((NCONS + 1) * 32)      // 288
#define GRID_SMS 148
#define SLICES_PER_WARP 16               // 128 k-slices / 8 warps
#define CHUNK_T 2                        // tiles per ticket
#define DSMEM_BYTES (NBUF * TILE_SMEM + 1024)  // 198400

__device__ double g_partials[GRID_SMS];
__device__ unsigned int g_counter = 0;
__device__ unsigned int g_ticket = 0;

__device__ __forceinline__ uint32_t smem_u32(const void* p) {
    uint32_t a;
    asm("{ .reg .u64 t; cvta.to.shared.u64 t, %1; cvt.u32.u64 %0, t; }" : "=r"(a) : "l"(p));
    return a;
}
__device__ __forceinline__ uint32_t elect_one() {
    uint32_t p;
    asm volatile("{ .reg .pred p; elect.sync _|p, 0xFFFFFFFF; selp.b32 %0, 1, 0, p; }" : "=r"(p));
    return p;
}
#define MBARRIER_INIT(a, n) \
    asm volatile("mbarrier.init.shared.b64 [%0], %1;" :: "r"(a), "r"((uint32_t)(n)) : "memory")
#define MBARRIER_EXPECT_TX(a, tx) \
    asm volatile("mbarrier.arrive.expect_tx.shared.b64 _, [%0], %1;" :: "r"(a), "r"((uint32_t)(tx)) : "memory")
#define MBARRIER_ARRIVE(a) \
    asm volatile("mbarrier.arrive.shared.b64 _, [%0];" :: "r"(a) : "memory")
#define MBAR_WAIT(a, par) do {                                              \
    uint32_t _m = (a), _p = (par), _d;                                      \
    asm volatile("{ .reg .pred p; mbarrier.try_wait.parity.acquire.cta.shared::cta.b64 p, [%1], %2;" \
                 " selp.b32 %0, 1, 0, p; }" : "=r"(_d) : "r"(_m), "r"(_p) : "memory");             \
    if (!_d) {                                                              \
        asm volatile("{ .reg .pred P1; WL_%=: mbarrier.try_wait.parity.acquire.cta.shared::cta.b64 P1, [%0], %1, 0x989680;" \
                     " @P1 bra.uni WD_%=; bra.uni WL_%=; WD_%=: }" :: "r"(_m), "r"(_p) : "memory"); \
    } } while (0)
__device__ __forceinline__ void bulk_copy(uint32_t dst, const void* src,
                                          uint32_t bytes, uint32_t mbar) {
    asm volatile("cp.async.bulk.shared::cta.global.mbarrier::complete_tx::bytes "
                 "[%0], [%1], %2, [%3];"
                 :: "r"(dst), "l"(src), "r"(bytes), "r"(mbar) : "memory");
}
// D(16x8) += A(16x8) * B(8x8); tf32 inputs as raw f32 bit patterns.
__device__ __forceinline__ void mma_tf32(float4& d,
                                         uint32_t a0, uint32_t a1, uint32_t a2, uint32_t a3,
                                         uint32_t b0, uint32_t b1) {
    asm volatile(
        "mma.sync.aligned.m16n8k8.row.col.f32.tf32.tf32.f32 "
        "{%0,%1,%2,%3}, {%4,%5,%6,%7}, {%8,%9}, {%0,%1,%2,%3};"
        : "+f"(d.x), "+f"(d.y), "+f"(d.z), "+f"(d.w)
        : "r"(a0), "r"(a1), "r"(a2), "r"(a3), "r"(b0), "r"(b1));
}

__global__ __launch_bounds__(NTHREADS, 1)
void qreg_r17_kernel(const float* __restrict__ hidden,
                     const float* __restrict__ Wm,
                     const float* __restrict__ bv,
                     float* __restrict__ out,
                     int B) {
    extern __shared__ char dsm_raw[];
    __shared__ __align__(8) uint64_t mb_full[NBUF], mb_empty[NBUF];
    __shared__ int s_tileidx[NBUF];
    __shared__ float4 sPart[3][NCONS][32];        // 3 rotating slots
    __shared__ double warp_locals[NCONS];
    __shared__ unsigned int is_last;

    const int tid = threadIdx.x;
    const int warp = tid >> 5, lane = tid & 31;
    const int bid = blockIdx.x;

    // 1024-align dynamic smem.
    const uint32_t raw = smem_u32(dsm_raw);
    const uint32_t base = (raw + 1023u) & ~1023u;
    const uint32_t tiles_u = base;                 // 3 tile buffers
    char* tiles_g = dsm_raw + (base - raw);

    if (tid == 0) {
        #pragma unroll
        for (int b = 0; b < NBUF; ++b) {
            MBARRIER_INIT(smem_u32(&mb_full[b]), 1);       // tx completes it
            MBARRIER_INIT(smem_u32(&mb_empty[b]), NCONS);  // 1 arrive/consumer
        }
    }
    if (tid < NCONS) warp_locals[tid] = 0.0;
    __syncthreads();

    const int ntiles = (B + TILE_ROWS - 1) / TILE_ROWS;

    if (warp == NCONS) {
        // ---- Producer: dynamic chunks of CHUNK_T tiles via global ticket,
        // next ticket prefetched before issuing the current chunk.
        if (elect_one()) {
            int i = 0;   // issued-slot sequence (consumers track the same i)
            int c = (int)atomicAdd(&g_ticket, 1u);
            while (c * CHUNK_T < ntiles) {
                const int next = (int)atomicAdd(&g_ticket, 1u);  // prefetch
                const int tb = c * CHUNK_T;
                int te = tb + CHUNK_T; if (te > ntiles) te = ntiles;
                for (int t = tb; t < te; ++t, ++i) {
                    const int buf = i % NBUF;
                    const uint32_t epar = (((i / NBUF) & 1) ^ 1);  // 1st pass free
                    MBAR_WAIT(smem_u32(&mb_empty[buf]), epar);
                    s_tileidx[buf] = t;   // ordered by TMA-complete release
                    const int row0 = t * TILE_ROWS;
                    int nv = B - row0; if (nv > TILE_ROWS) nv = TILE_ROWS;
                    MBARRIER_EXPECT_TX(smem_u32(&mb_full[buf]),
                                       (uint32_t)nv * ROW_BYTES);
                    const uint32_t dst0 = tiles_u + (uint32_t)buf * TILE_SMEM;
                    const char* src0 = (const char*)hidden
                                     + (size_t)row0 * ROW_BYTES;
                    #pragma unroll
                    for (int r = 0; r < TILE_ROWS; ++r) {
                        if (r < nv)
                            bulk_copy(dst0 + (uint32_t)r * ROW_STRIDE,
                                      src0 + (size_t)r * ROW_BYTES,
                                      ROW_BYTES, smem_u32(&mb_full[buf]));
                    }
                }
                c = next;
            }
            // Sentinel: complete the next slot without TMA.
            const int buf = i % NBUF;
            const uint32_t epar = (((i / NBUF) & 1) ^ 1);
            MBAR_WAIT(smem_u32(&mb_empty[buf]), epar);
            s_tileidx[buf] = -1;
            MBARRIER_ARRIVE(smem_u32(&mb_full[buf]));   // release + complete
        }
    } else {
        // ---- Consumer warp w: K-range [w*128, (w+1)*128) of every tile.
        const int rl = lane >> 2;           // fragment row 0..7
        const int kl = lane & 3;            // fragment k-lane 0..3
        const float b0v = bv[2 * kl];
        const float b1v = bv[2 * kl + 1];

        // B fragments in registers: slice j (global slice s = warp*16 + j):
        // b0 = W[lane/4][8s + lane%4], b1 = W[lane/4][8s + lane%4 + 4].
        uint32_t bf0[SLICES_PER_WARP], bf1[SLICES_PER_WARP];
        {
            const int n = lane >> 2;
            const float* wr = Wm + n * HDIM + (warp * SLICES_PER_WARP) * 8 + kl;
            #pragma unroll
            for (int j = 0; j < SLICES_PER_WARP; ++j) {
                bf0[j] = __float_as_uint(wr[j * 8]);
                bf1[j] = __float_as_uint(wr[j * 8 + 4]);
            }
        }

        double local = 0.0;
        for (int i = 0;; ++i) {
            const int buf = i % NBUF;
            const uint32_t fpar = (i / NBUF) & 1;
            MBAR_WAIT(smem_u32(&mb_full[buf]), fpar);
            const int t = s_tileidx[buf];
            if (t < 0) break;

            const char* Tb = tiles_g + buf * TILE_SMEM;
            const char* pa = Tb + rl * ROW_STRIDE + kl * 4
                           + warp * (SLICES_PER_WARP * 32);

            float4 acc0 = make_float4(0.f, 0.f, 0.f, 0.f);
            float4 acc1 = make_float4(0.f, 0.f, 0.f, 0.f);

            #pragma unroll
            for (int j = 0; j < SLICES_PER_WARP; ++j) {
                const char* p = pa + j * 32;
                const uint32_t a0 = *reinterpret_cast<const uint32_t*>(p);
                const uint32_t a1 = *reinterpret_cast<const uint32_t*>(p + 8 * ROW_STRIDE);
                const uint32_t a2 = *reinterpret_cast<const uint32_t*>(p + 16);
                const uint32_t a3 = *reinterpret_cast<const uint32_t*>(p + 8 * ROW_STRIDE + 16);
                float4& acc = (j & 1) ? acc1 : acc0;
                mma_tf32(acc, a0, a1, a2, a3, bf0[j], bf1[j]);
            }
            // Reads done -> free the buffer slot for the producer.
            if (elect_one()) MBARRIER_ARRIVE(smem_u32(&mb_empty[buf]));

            const int ps = i % 3;           // sPart rotating slot
            float4 acc;
            acc.x = acc0.x + acc1.x; acc.y = acc0.y + acc1.y;
            acc.z = acc0.z + acc1.z; acc.w = acc0.w + acc1.w;
            sPart[ps][warp][lane] = acc;
            // One consumer-scope barrier: all partials for tile i stored.
            asm volatile("bar.sync 1, %0;" :: "n"(NCONS * 32) : "memory");

            // Rotated epilogue: warp (i%8) handles tile i off-critical-path.
            if (warp == (i & 7)) {
                float4 a = sPart[ps][0][lane];
                #pragma unroll
                for (int w = 1; w < NCONS; ++w) {
                    const float4 b = sPart[ps][w][lane];
                    a.x += b.x; a.y += b.y; a.z += b.z; a.w += b.w;
                }
                const float tA0 = a.x + b0v, tA1 = a.y + b1v;
                const float tB0 = a.z + b0v, tB1 = a.w + b1v;
                float pA = 0.25f * (1.0f + __cosf(tA0)) * (1.0f + __cosf(tA1));
                float pB = 0.25f * (1.0f + __cosf(tB0)) * (1.0f + __cosf(tB1));
                #pragma unroll
                for (int d = 1; d <= 2; d <<= 1) {
                    pA *= __shfl_xor_sync(0xffffffffu, pA, d);
                    pB *= __shfl_xor_sync(0xffffffffu, pB, d);
                }
                const int rowA = t * TILE_ROWS + rl;
                const int rowB = rowA + 8;
                float sv = ((rowA < B) ? (1.0f - pA) : 0.0f)
                         + ((rowB < B) ? (1.0f - pB) : 0.0f);
                #pragma unroll
                for (int d = 1; d <= 16; d <<= 1)
                    sv += __shfl_xor_sync(0xffffffffu, sv, d);
                local += (double)sv * 0.25;   // quad replication
            }
        }
        if (lane == 0) warp_locals[warp] = local;
    }
    __syncthreads();

    if (tid == 0) {
        double bsum = 0.0;
        #pragma unroll
        for (int w = 0; w < NCONS; ++w) bsum += warp_locals[w];
        g_partials[bid] = bsum;
        __threadfence();
        const unsigned int prev = atomicAdd(&g_counter, 1u);
        is_last = (prev == gridDim.x - 1) ? 1u : 0u;
    }
    __syncthreads();

    if (is_last) {
        __threadfence();
        const volatile double* vp = g_partials;
        double ssum = 0.0;
        for (int i = tid; i < (int)gridDim.x; i += NTHREADS) ssum += vp[i];
        #pragma unroll
        for (int d = 16; d > 0; d >>= 1)
            ssum += __shfl_down_sync(0xffffffffu, ssum, d);
        __shared__ double fin[NCONS + 1];
        if (lane == 0) fin[warp] = ssum;
        __syncthreads();
        if (tid == 0) {
            double tt = 0.0;
            #pragma unroll
            for (int w = 0; w < NCONS + 1; ++w) tt += fin[w];
            out[0] = (float)(tt / (double)B);
            g_counter = 0;   // reset for graph replay
            g_ticket = 0;
        }
    }
}

extern "C" void kernel_launch(void* const* d_in, const int* in_sizes, int n_in,
                              void* d_out, int out_size) {
    const float* hidden = (const float*)d_in[0];   // [B, H] f32
    const float* Wm     = (const float*)d_in[1];   // [Q, H] f32
    const float* bv     = (const float*)d_in[2];   // [Q]    f32
    float* out = (float*)d_out;

    const int B = in_sizes[0] / HDIM;

    static bool attr_set = false;
    if (!attr_set) {
        cudaFuncSetAttribute(qreg_r17_kernel,
                             cudaFuncAttributeMaxDynamicSharedMemorySize,
                             DSMEM_BYTES);
        attr_set = true;
    }

    qreg_r17_kernel<<<GRID_SMS, NTHREADS, DSMEM_BYTES>>>(hidden, Wm, bv, out, B);
}